// round 2
// baseline (speedup 1.0000x reference)
#include <cuda_runtime.h>
#include <cuda_bf16.h>

// Problem constants
#define BB   8
#define CIN  64
#define HH   64
#define WW   64
#define OCH_OFF 1152          // 2*C*KK
#define OCH_TOT 1728
#define OC_FIN  128
#define MAXOFF  16.0f

// Scratch: combined offset(first 1152 ch, clipped) + mask(next 576 ch)
__device__ float g_om[(size_t)BB * OCH_TOT * HH * WW];
// transposed final-conv weights: g_wt[ck][oc]
__device__ float g_wt[576 * 128];

// ---------------- packed f32x2 helpers ----------------
__device__ __forceinline__ unsigned long long ffma2(unsigned long long a,
                                                    unsigned long long b,
                                                    unsigned long long c) {
    unsigned long long d;
    asm("fma.rn.f32x2 %0, %1, %2, %3;" : "=l"(d) : "l"(a), "l"(b), "l"(c));
    return d;
}
__device__ __forceinline__ unsigned long long pack2(float lo, float hi) {
    unsigned long long d;
    asm("mov.b64 %0, {%1, %2};" : "=l"(d) : "f"(lo), "f"(hi));
    return d;
}
__device__ __forceinline__ void unpack2(unsigned long long v, float& lo, float& hi) {
    asm("mov.b64 {%0, %1}, %2;" : "=f"(lo), "=f"(hi) : "l"(v));
}

// ---------------------------------------------------------------------------
// Kernel 1: fused 3x3 conv producing offset+mask channels, FFMA2 inner loop.
// CTA tile: 64 oc x 64 px (one row y). 256 threads, 4oc x 4px each.
// Vector lanes run along oc (weight pairs pre-packed in smem).
// ---------------------------------------------------------------------------
__global__ __launch_bounds__(256) void conv_om_kernel(
    const float* __restrict__ x,
    const float* __restrict__ w_off,
    const float* __restrict__ b_off,
    const float* __restrict__ w_mod,
    const float* __restrict__ b_mod)
{
    const int ocBlk = blockIdx.x;           // 0..26
    const int y     = blockIdx.y;
    const int b     = blockIdx.z;
    const int ocBase = ocBlk * 64;
    const int tid = threadIdx.x;
    const int tx  = tid & 15;
    const int ty  = tid >> 4;
    const int px0  = tx * 4;
    const int ocL0 = ty * 4;

    // whole CTA is uniformly in offset- or mask-channel range (1152 = 18*64)
    const bool isOff = (ocBase < OCH_OFF);
    const float* wsrc = isOff ? w_off : w_mod;
    const float* bsrc = isOff ? b_off : b_mod;
    const int rAdj = isOff ? ocBase : (ocBase - OCH_OFF);

    __shared__ __align__(16) float xs[2][3][68];   // 2 ch, 3 halo rows
    __shared__ __align__(16) float ws[2][9][64];   // 2 ch, tap-major weights

    unsigned long long acc2[2][4];                 // [oc pair][px]
    const unsigned long long z2 = 0ull;
#pragma unroll
    for (int p = 0; p < 2; p++)
#pragma unroll
        for (int j = 0; j < 4; j++) acc2[p][j] = z2;

    for (int c0 = 0; c0 < CIN; c0 += 2) {
        // x rows for 2 channels
        for (int idx = tid; idx < 2 * 3 * 66; idx += 256) {
            int cc = idx / 198, rem = idx % 198;
            int r = rem / 66, j = rem % 66;
            int yy = y + r - 1;
            float v = 0.f;
            if (j >= 1 && j <= 64 && yy >= 0 && yy < HH)
                v = __ldg(&x[(((size_t)b * CIN + (c0 + cc)) * HH + yy) * WW + (j - 1)]);
            xs[cc][r][j] = v;
        }
        // weights: ws[cc][t][ocl] = w[(rAdj+ocl)][c0+cc][t]
        for (int idx = tid; idx < 2 * 9 * 64; idx += 256) {
            int ocl = idx & 63, t = (idx >> 6) % 9, cc = idx / 576;
            ws[cc][t][ocl] = __ldg(&wsrc[((size_t)(rAdj + ocl) * CIN + (c0 + cc)) * 9 + t]);
        }
        __syncthreads();

#pragma unroll
        for (int cc = 0; cc < 2; cc++) {
#pragma unroll
            for (int ki = 0; ki < 3; ki++) {
                float4 xa = *(const float4*)&xs[cc][ki][px0];
                float2 xb = *(const float2*)&xs[cc][ki][px0 + 4];
                unsigned long long xp[6];
                xp[0] = pack2(xa.x, xa.x);
                xp[1] = pack2(xa.y, xa.y);
                xp[2] = pack2(xa.z, xa.z);
                xp[3] = pack2(xa.w, xa.w);
                xp[4] = pack2(xb.x, xb.x);
                xp[5] = pack2(xb.y, xb.y);
#pragma unroll
                for (int kj = 0; kj < 3; kj++) {
                    ulonglong2 wq = *(const ulonglong2*)&ws[cc][ki * 3 + kj][ocL0];
#pragma unroll
                    for (int j = 0; j < 4; j++) {
                        acc2[0][j] = ffma2(wq.x, xp[j + kj], acc2[0][j]);
                        acc2[1][j] = ffma2(wq.y, xp[j + kj], acc2[1][j]);
                    }
                }
            }
        }
        __syncthreads();
    }

    // epilogue: unpack, bias, clip, vector store
    float o[4][4];
#pragma unroll
    for (int p = 0; p < 2; p++)
#pragma unroll
        for (int j = 0; j < 4; j++)
            unpack2(acc2[p][j], o[2 * p][j], o[2 * p + 1][j]);

#pragma unroll
    for (int i = 0; i < 4; i++) {
        int r = ocBase + ocL0 + i;
        float bias = __ldg(&bsrc[rAdj + ocL0 + i]);
        float4 v;
        v.x = o[i][0] + bias; v.y = o[i][1] + bias;
        v.z = o[i][2] + bias; v.w = o[i][3] + bias;
        if (isOff) {
            v.x = fminf(fmaxf(v.x, -MAXOFF), MAXOFF);
            v.y = fminf(fmaxf(v.y, -MAXOFF), MAXOFF);
            v.z = fminf(fmaxf(v.z, -MAXOFF), MAXOFF);
            v.w = fminf(fmaxf(v.w, -MAXOFF), MAXOFF);
        }
        *(float4*)&g_om[(((size_t)b * OCH_TOT + r) * HH + y) * WW + px0] = v;
    }
}

// ---------------------------------------------------------------------------
// Kernel 2: transpose w_conv [128][576] -> g_wt [576][128]
// ---------------------------------------------------------------------------
__global__ void transpose_wconv(const float* __restrict__ w_conv)
{
    int i = blockIdx.x * 256 + threadIdx.x;
    if (i < OC_FIN * 576) {
        int oc = i / 576, ck = i % 576;
        g_wt[ck * 128 + oc] = w_conv[i];
    }
}

// ---------------------------------------------------------------------------
// Kernel 3: deformable bilinear sampling + final GEMM (FFMA2 GEMM stage).
// CTA = one (b, y) row: 64 px x 128 oc. 256 threads.
// ---------------------------------------------------------------------------
__global__ __launch_bounds__(256) void deform_gemm_kernel(
    const float* __restrict__ x,
    float* __restrict__ out)
{
    const int y = blockIdx.x;
    const int b = blockIdx.y;
    const int tid = threadIdx.x;
    const int tx = tid & 15;
    const int ty = tid >> 4;
    const int px0 = tx * 4;
    const int oc0 = ty * 8;

    __shared__ __align__(16) float ss[4 * 9 * 64];   // [cc][k][px]
    __shared__ __align__(16) float wcs[36][128];     // [ck][oc]

    unsigned long long acc2[4][4];                   // [oc pair][px]
#pragma unroll
    for (int p = 0; p < 4; p++)
#pragma unroll
        for (int j = 0; j < 4; j++) acc2[p][j] = 0ull;

    const float* xb  = x + (size_t)b * CIN * HH * WW;
    const float* omb = g_om + (size_t)b * OCH_TOT * HH * WW;

    for (int c0 = 0; c0 < CIN; c0 += 4) {
        for (int idx = tid; idx < 36 * 128; idx += 256) {
            ((float*)wcs)[idx] = g_wt[(c0 * 9 + (idx >> 7)) * 128 + (idx & 127)];
        }
        for (int s = tid; s < 4 * 9 * 64; s += 256) {
            int px = s & 63;
            int k  = (s >> 6) % 9;
            int cc = s / 576;
            int c  = c0 + cc;
            int ki = k / 3, kj = k % 3;
            float dy = omb[(((size_t)c * 18 + k * 2 + 0) * HH + y) * WW + px];
            float dx = omb[(((size_t)c * 18 + k * 2 + 1) * HH + y) * WW + px];
            float m  = omb[(((size_t)OCH_OFF + c * 9 + k) * HH + y) * WW + px];
            float py  = dy + (float)(y - 1 + ki);
            float pxf = dx + (float)(px - 1 + kj);
            float v = 0.f;
            if (py > -1.f && py < (float)HH && pxf > -1.f && pxf < (float)WW) {
                float y0f = floorf(py), x0f = floorf(pxf);
                int y0 = (int)y0f, x0 = (int)x0f;
                float wy = py - y0f, wx = pxf - x0f;
                const float* xc = xb + (size_t)c * HH * WW;
                float v00 = 0.f, v01 = 0.f, v10 = 0.f, v11 = 0.f;
                bool y0i = (y0 >= 0) & (y0 < HH);
                bool y1i = (y0 + 1 >= 0) & (y0 + 1 < HH);
                bool x0i = (x0 >= 0) & (x0 < WW);
                bool x1i = (x0 + 1 >= 0) & (x0 + 1 < WW);
                if (y0i & x0i) v00 = __ldg(&xc[y0 * WW + x0]);
                if (y0i & x1i) v01 = __ldg(&xc[y0 * WW + x0 + 1]);
                if (y1i & x0i) v10 = __ldg(&xc[(y0 + 1) * WW + x0]);
                if (y1i & x1i) v11 = __ldg(&xc[(y0 + 1) * WW + x0 + 1]);
                v = (1.f - wy) * ((1.f - wx) * v00 + wx * v01)
                  +        wy  * ((1.f - wx) * v10 + wx * v11);
            }
            ss[s] = v * m;
        }
        __syncthreads();

#pragma unroll
        for (int ck = 0; ck < 36; ck++) {
            float4 sv4 = *(const float4*)&ss[ck * 64 + px0];
            unsigned long long sp[4];
            sp[0] = pack2(sv4.x, sv4.x);
            sp[1] = pack2(sv4.y, sv4.y);
            sp[2] = pack2(sv4.z, sv4.z);
            sp[3] = pack2(sv4.w, sv4.w);
            ulonglong2 w0 = *(const ulonglong2*)&wcs[ck][oc0];
            ulonglong2 w1 = *(const ulonglong2*)&wcs[ck][oc0 + 4];
#pragma unroll
            for (int j = 0; j < 4; j++) {
                acc2[0][j] = ffma2(w0.x, sp[j], acc2[0][j]);
                acc2[1][j] = ffma2(w0.y, sp[j], acc2[1][j]);
                acc2[2][j] = ffma2(w1.x, sp[j], acc2[2][j]);
                acc2[3][j] = ffma2(w1.y, sp[j], acc2[3][j]);
            }
        }
        __syncthreads();
    }

    // unpack + vector store: out[b][oc][y][px]
#pragma unroll
    for (int p = 0; p < 4; p++) {
        float lo[4], hi[4];
#pragma unroll
        for (int j = 0; j < 4; j++) unpack2(acc2[p][j], lo[j], hi[j]);
        float4 vlo = make_float4(lo[0], lo[1], lo[2], lo[3]);
        float4 vhi = make_float4(hi[0], hi[1], hi[2], hi[3]);
        int oc = oc0 + 2 * p;
        *(float4*)&out[(((size_t)b * OC_FIN + oc) * HH + y) * WW + px0] = vlo;
        *(float4*)&out[(((size_t)b * OC_FIN + oc + 1) * HH + y) * WW + px0] = vhi;
    }
}

// ---------------------------------------------------------------------------
extern "C" void kernel_launch(void* const* d_in, const int* in_sizes, int n_in,
                              void* d_out, int out_size)
{
    const float* x      = (const float*)d_in[0];
    const float* w_off  = (const float*)d_in[1];
    const float* b_off  = (const float*)d_in[2];
    const float* w_mod  = (const float*)d_in[3];
    const float* b_mod  = (const float*)d_in[4];
    const float* w_conv = (const float*)d_in[5];
    float* out = (float*)d_out;

    dim3 g1(OCH_TOT / 64, HH, BB);
    conv_om_kernel<<<g1, 256>>>(x, w_off, b_off, w_mod, b_mod);

    transpose_wconv<<<(OC_FIN * 576 + 255) / 256, 256>>>(w_conv);

    dim3 g3(HH, BB);
    deform_gemm_kernel<<<g3, 256>>>(x, out);
}

// round 3
// speedup vs baseline: 1.0018x; 1.0018x over previous
#include <cuda_runtime.h>
#include <cuda_bf16.h>

// Problem constants
#define BB   8
#define CIN  64
#define HH   64
#define WW   64
#define OCH_OFF 1152          // 2*C*KK
#define OCH_TOT 1728
#define OC_FIN  128
#define MAXOFF  16.0f

// Scratch: combined offset(first 1152 ch, clipped) + mask(next 576 ch)
__device__ float g_om[(size_t)BB * OCH_TOT * HH * WW];
// transposed final-conv weights: g_wt[ck][oc]
__device__ float g_wt[576 * 128];

// ---------------- packed f32x2 helpers ----------------
__device__ __forceinline__ unsigned long long ffma2(unsigned long long a,
                                                    unsigned long long b,
                                                    unsigned long long c) {
    unsigned long long d;
    asm("fma.rn.f32x2 %0, %1, %2, %3;" : "=l"(d) : "l"(a), "l"(b), "l"(c));
    return d;
}
__device__ __forceinline__ unsigned long long pack2(float lo, float hi) {
    unsigned long long d;
    asm("mov.b64 %0, {%1, %2};" : "=l"(d) : "f"(lo), "f"(hi));
    return d;
}
__device__ __forceinline__ void unpack2(unsigned long long v, float& lo, float& hi) {
    asm("mov.b64 {%0, %1}, %2;" : "=f"(lo), "=f"(hi) : "l"(v));
}

// ---------------------------------------------------------------------------
// Kernel 1: fused 3x3 conv producing offset+mask channels, FFMA2 inner loop.
// CTA tile: 64 oc x 64 px (one row y). 256 threads, 4oc x 4px each.
// Vector lanes run along oc (weight pairs pre-packed in smem).
// ---------------------------------------------------------------------------
__global__ __launch_bounds__(256) void conv_om_kernel(
    const float* __restrict__ x,
    const float* __restrict__ w_off,
    const float* __restrict__ b_off,
    const float* __restrict__ w_mod,
    const float* __restrict__ b_mod)
{
    const int ocBlk = blockIdx.x;           // 0..26
    const int y     = blockIdx.y;
    const int b     = blockIdx.z;
    const int ocBase = ocBlk * 64;
    const int tid = threadIdx.x;
    const int tx  = tid & 15;
    const int ty  = tid >> 4;
    const int px0  = tx * 4;
    const int ocL0 = ty * 4;

    // whole CTA is uniformly in offset- or mask-channel range (1152 = 18*64)
    const bool isOff = (ocBase < OCH_OFF);
    const float* wsrc = isOff ? w_off : w_mod;
    const float* bsrc = isOff ? b_off : b_mod;
    const int rAdj = isOff ? ocBase : (ocBase - OCH_OFF);

    __shared__ __align__(16) float xs[2][3][68];   // 2 ch, 3 halo rows
    __shared__ __align__(16) float ws[2][9][64];   // 2 ch, tap-major weights

    unsigned long long acc2[2][4];                 // [oc pair][px]
    const unsigned long long z2 = 0ull;
#pragma unroll
    for (int p = 0; p < 2; p++)
#pragma unroll
        for (int j = 0; j < 4; j++) acc2[p][j] = z2;

    for (int c0 = 0; c0 < CIN; c0 += 2) {
        // x rows for 2 channels
        for (int idx = tid; idx < 2 * 3 * 66; idx += 256) {
            int cc = idx / 198, rem = idx % 198;
            int r = rem / 66, j = rem % 66;
            int yy = y + r - 1;
            float v = 0.f;
            if (j >= 1 && j <= 64 && yy >= 0 && yy < HH)
                v = __ldg(&x[(((size_t)b * CIN + (c0 + cc)) * HH + yy) * WW + (j - 1)]);
            xs[cc][r][j] = v;
        }
        // weights: ws[cc][t][ocl] = w[(rAdj+ocl)][c0+cc][t]
        for (int idx = tid; idx < 2 * 9 * 64; idx += 256) {
            int ocl = idx & 63, t = (idx >> 6) % 9, cc = idx / 576;
            ws[cc][t][ocl] = __ldg(&wsrc[((size_t)(rAdj + ocl) * CIN + (c0 + cc)) * 9 + t]);
        }
        __syncthreads();

#pragma unroll
        for (int cc = 0; cc < 2; cc++) {
#pragma unroll
            for (int ki = 0; ki < 3; ki++) {
                float4 xa = *(const float4*)&xs[cc][ki][px0];
                float2 xb = *(const float2*)&xs[cc][ki][px0 + 4];
                unsigned long long xp[6];
                xp[0] = pack2(xa.x, xa.x);
                xp[1] = pack2(xa.y, xa.y);
                xp[2] = pack2(xa.z, xa.z);
                xp[3] = pack2(xa.w, xa.w);
                xp[4] = pack2(xb.x, xb.x);
                xp[5] = pack2(xb.y, xb.y);
#pragma unroll
                for (int kj = 0; kj < 3; kj++) {
                    ulonglong2 wq = *(const ulonglong2*)&ws[cc][ki * 3 + kj][ocL0];
#pragma unroll
                    for (int j = 0; j < 4; j++) {
                        acc2[0][j] = ffma2(wq.x, xp[j + kj], acc2[0][j]);
                        acc2[1][j] = ffma2(wq.y, xp[j + kj], acc2[1][j]);
                    }
                }
            }
        }
        __syncthreads();
    }

    // epilogue: unpack, bias, clip, vector store
    float o[4][4];
#pragma unroll
    for (int p = 0; p < 2; p++)
#pragma unroll
        for (int j = 0; j < 4; j++)
            unpack2(acc2[p][j], o[2 * p][j], o[2 * p + 1][j]);

#pragma unroll
    for (int i = 0; i < 4; i++) {
        int r = ocBase + ocL0 + i;
        float bias = __ldg(&bsrc[rAdj + ocL0 + i]);
        float4 v;
        v.x = o[i][0] + bias; v.y = o[i][1] + bias;
        v.z = o[i][2] + bias; v.w = o[i][3] + bias;
        if (isOff) {
            v.x = fminf(fmaxf(v.x, -MAXOFF), MAXOFF);
            v.y = fminf(fmaxf(v.y, -MAXOFF), MAXOFF);
            v.z = fminf(fmaxf(v.z, -MAXOFF), MAXOFF);
            v.w = fminf(fmaxf(v.w, -MAXOFF), MAXOFF);
        }
        *(float4*)&g_om[(((size_t)b * OCH_TOT + r) * HH + y) * WW + px0] = v;
    }
}

// ---------------------------------------------------------------------------
// Kernel 2: transpose w_conv [128][576] -> g_wt [576][128]
// ---------------------------------------------------------------------------
__global__ void transpose_wconv(const float* __restrict__ w_conv)
{
    int i = blockIdx.x * 256 + threadIdx.x;
    if (i < OC_FIN * 576) {
        int oc = i / 576, ck = i % 576;
        g_wt[ck * 128 + oc] = w_conv[i];
    }
}

// ---------------------------------------------------------------------------
// Kernel 3: deformable bilinear sampling + final GEMM (FFMA2 GEMM stage).
// CTA = one (b, y) row: 64 px x 128 oc. 256 threads.
// ---------------------------------------------------------------------------
__global__ __launch_bounds__(256) void deform_gemm_kernel(
    const float* __restrict__ x,
    float* __restrict__ out)
{
    const int y = blockIdx.x;
    const int b = blockIdx.y;
    const int tid = threadIdx.x;
    const int tx = tid & 15;
    const int ty = tid >> 4;
    const int px0 = tx * 4;
    const int oc0 = ty * 8;

    __shared__ __align__(16) float ss[4 * 9 * 64];   // [cc][k][px]
    __shared__ __align__(16) float wcs[36][128];     // [ck][oc]

    unsigned long long acc2[4][4];                   // [oc pair][px]
#pragma unroll
    for (int p = 0; p < 4; p++)
#pragma unroll
        for (int j = 0; j < 4; j++) acc2[p][j] = 0ull;

    const float* xb  = x + (size_t)b * CIN * HH * WW;
    const float* omb = g_om + (size_t)b * OCH_TOT * HH * WW;

    for (int c0 = 0; c0 < CIN; c0 += 4) {
        for (int idx = tid; idx < 36 * 128; idx += 256) {
            ((float*)wcs)[idx] = g_wt[(c0 * 9 + (idx >> 7)) * 128 + (idx & 127)];
        }
        for (int s = tid; s < 4 * 9 * 64; s += 256) {
            int px = s & 63;
            int k  = (s >> 6) % 9;
            int cc = s / 576;
            int c  = c0 + cc;
            int ki = k / 3, kj = k % 3;
            float dy = omb[(((size_t)c * 18 + k * 2 + 0) * HH + y) * WW + px];
            float dx = omb[(((size_t)c * 18 + k * 2 + 1) * HH + y) * WW + px];
            float m  = omb[(((size_t)OCH_OFF + c * 9 + k) * HH + y) * WW + px];
            float py  = dy + (float)(y - 1 + ki);
            float pxf = dx + (float)(px - 1 + kj);
            float v = 0.f;
            if (py > -1.f && py < (float)HH && pxf > -1.f && pxf < (float)WW) {
                float y0f = floorf(py), x0f = floorf(pxf);
                int y0 = (int)y0f, x0 = (int)x0f;
                float wy = py - y0f, wx = pxf - x0f;
                const float* xc = xb + (size_t)c * HH * WW;
                float v00 = 0.f, v01 = 0.f, v10 = 0.f, v11 = 0.f;
                bool y0i = (y0 >= 0) & (y0 < HH);
                bool y1i = (y0 + 1 >= 0) & (y0 + 1 < HH);
                bool x0i = (x0 >= 0) & (x0 < WW);
                bool x1i = (x0 + 1 >= 0) & (x0 + 1 < WW);
                if (y0i & x0i) v00 = __ldg(&xc[y0 * WW + x0]);
                if (y0i & x1i) v01 = __ldg(&xc[y0 * WW + x0 + 1]);
                if (y1i & x0i) v10 = __ldg(&xc[(y0 + 1) * WW + x0]);
                if (y1i & x1i) v11 = __ldg(&xc[(y0 + 1) * WW + x0 + 1]);
                v = (1.f - wy) * ((1.f - wx) * v00 + wx * v01)
                  +        wy  * ((1.f - wx) * v10 + wx * v11);
            }
            ss[s] = v * m;
        }
        __syncthreads();

#pragma unroll
        for (int ck = 0; ck < 36; ck++) {
            float4 sv4 = *(const float4*)&ss[ck * 64 + px0];
            unsigned long long sp[4];
            sp[0] = pack2(sv4.x, sv4.x);
            sp[1] = pack2(sv4.y, sv4.y);
            sp[2] = pack2(sv4.z, sv4.z);
            sp[3] = pack2(sv4.w, sv4.w);
            ulonglong2 w0 = *(const ulonglong2*)&wcs[ck][oc0];
            ulonglong2 w1 = *(const ulonglong2*)&wcs[ck][oc0 + 4];
#pragma unroll
            for (int j = 0; j < 4; j++) {
                acc2[0][j] = ffma2(w0.x, sp[j], acc2[0][j]);
                acc2[1][j] = ffma2(w0.y, sp[j], acc2[1][j]);
                acc2[2][j] = ffma2(w1.x, sp[j], acc2[2][j]);
                acc2[3][j] = ffma2(w1.y, sp[j], acc2[3][j]);
            }
        }
        __syncthreads();
    }

    // unpack + vector store: out[b][oc][y][px]
#pragma unroll
    for (int p = 0; p < 4; p++) {
        float lo[4], hi[4];
#pragma unroll
        for (int j = 0; j < 4; j++) unpack2(acc2[p][j], lo[j], hi[j]);
        float4 vlo = make_float4(lo[0], lo[1], lo[2], lo[3]);
        float4 vhi = make_float4(hi[0], hi[1], hi[2], hi[3]);
        int oc = oc0 + 2 * p;
        *(float4*)&out[(((size_t)b * OC_FIN + oc) * HH + y) * WW + px0] = vlo;
        *(float4*)&out[(((size_t)b * OC_FIN + oc + 1) * HH + y) * WW + px0] = vhi;
    }
}

// ---------------------------------------------------------------------------
extern "C" void kernel_launch(void* const* d_in, const int* in_sizes, int n_in,
                              void* d_out, int out_size)
{
    const float* x      = (const float*)d_in[0];
    const float* w_off  = (const float*)d_in[1];
    const float* b_off  = (const float*)d_in[2];
    const float* w_mod  = (const float*)d_in[3];
    const float* b_mod  = (const float*)d_in[4];
    const float* w_conv = (const float*)d_in[5];
    float* out = (float*)d_out;

    dim3 g1(OCH_TOT / 64, HH, BB);
    conv_om_kernel<<<g1, 256>>>(x, w_off, b_off, w_mod, b_mod);

    transpose_wconv<<<(OC_FIN * 576 + 255) / 256, 256>>>(w_conv);

    dim3 g3(HH, BB);
    deform_gemm_kernel<<<g3, 256>>>(x, out);
}

// round 6
// speedup vs baseline: 3.2189x; 3.2132x over previous
#include <cuda_runtime.h>
#include <cuda_bf16.h>
#include <cstdint>

// Problem constants
#define BB   8
#define CIN  64
#define HH   64
#define WW   64
#define OCH_OFF 1152
#define OCH_TOT 1728
#define OCP     1792          // padded oc (14 * 128)
#define OC_FIN  128
#define MAXOFF  16.0f

// Scratch
__device__ float g_om[(size_t)BB * OCH_TOT * HH * WW];   // conv out [b][r][y][x]
__device__ float g_wt[576 * 128];                        // w_conv transposed
// shifted x, chunked: g_xt2[kj][b][yy 0..65][cc 0..3][px 0..63][cic 0..15]
//   value = x[b][cc*16+cic][yy-1][px+kj-1]  (0 if OOB), bf16 hi/lo
__device__ __nv_bfloat16 g_xt2_hi[3 * 8 * 66 * 4 * 64 * 16];
__device__ __nv_bfloat16 g_xt2_lo[3 * 8 * 66 * 4 * 64 * 16];
// conv weights, chunked: g_wa2[t][cc][ocp][cic], bf16 hi/lo (zeros oc>=1728)
__device__ __nv_bfloat16 g_wa2_hi[9 * 4 * OCP * 16];
__device__ __nv_bfloat16 g_wa2_lo[9 * 4 * OCP * 16];

// ======================= helpers =======================
__device__ __forceinline__ uint32_t smem_u32(const void* p) {
    uint32_t a;
    asm("{ .reg .u64 t; cvta.to.shared.u64 t, %1; cvt.u32.u64 %0, t; }"
        : "=r"(a) : "l"(p));
    return a;
}
__device__ __forceinline__ void ldm_x4(uint32_t* r, uint32_t addr) {
    asm volatile("ldmatrix.sync.aligned.m8n8.x4.shared.b16 {%0,%1,%2,%3}, [%4];"
                 : "=r"(r[0]), "=r"(r[1]), "=r"(r[2]), "=r"(r[3]) : "r"(addr));
}
__device__ __forceinline__ void mma_bf16(float* d, const uint32_t* a,
                                         uint32_t b0, uint32_t b1) {
    asm volatile(
        "mma.sync.aligned.m16n8k16.row.col.f32.bf16.bf16.f32 "
        "{%0,%1,%2,%3}, {%4,%5,%6,%7}, {%8,%9}, {%0,%1,%2,%3};"
        : "+f"(d[0]), "+f"(d[1]), "+f"(d[2]), "+f"(d[3])
        : "r"(a[0]), "r"(a[1]), "r"(a[2]), "r"(a[3]), "r"(b0), "r"(b1));
}

// ---------------- packed f32x2 helpers (deform kernel) ----------------
__device__ __forceinline__ unsigned long long ffma2(unsigned long long a,
                                                    unsigned long long b,
                                                    unsigned long long c) {
    unsigned long long d;
    asm("fma.rn.f32x2 %0, %1, %2, %3;" : "=l"(d) : "l"(a), "l"(b), "l"(c));
    return d;
}
__device__ __forceinline__ unsigned long long pack2(float lo, float hi) {
    unsigned long long d;
    asm("mov.b64 %0, {%1, %2};" : "=l"(d) : "f"(lo), "f"(hi));
    return d;
}
__device__ __forceinline__ void unpack2(unsigned long long v, float& lo, float& hi) {
    asm("mov.b64 {%0, %1}, %2;" : "=f"(lo), "=f"(hi) : "l"(v));
}

// ======================= Prep kernels =======================
__global__ void prep_xt2(const float* __restrict__ x) {
    int i = blockIdx.x * 256 + threadIdx.x;
    const int TOT = 3 * 8 * 66 * 4 * 64 * 16;
    if (i >= TOT) return;
    int cic = i & 15;
    int t1 = i >> 4;
    int px = t1 & 63;
    int t2 = t1 >> 6;
    int cc = t2 & 3;
    int t3 = t2 >> 2;
    int yy = t3 % 66;
    int t4 = t3 / 66;
    int b  = t4 & 7;
    int kj = t4 >> 3;
    int c = cc * 16 + cic;
    int sy = yy - 1, sx = px + kj - 1;
    float v = 0.f;
    if (sy >= 0 && sy < HH && sx >= 0 && sx < WW)
        v = x[(((size_t)b * CIN + c) * HH + sy) * WW + sx];
    __nv_bfloat16 h = __float2bfloat16(v);
    g_xt2_hi[i] = h;
    g_xt2_lo[i] = __float2bfloat16(v - __bfloat162float(h));
}

__global__ void prep_w2(const float* __restrict__ w_off, const float* __restrict__ w_mod) {
    int i = blockIdx.x * 256 + threadIdx.x;
    const int TOT = 9 * 4 * OCP * 16;
    if (i >= TOT) return;
    int cic = i & 15;
    int t1 = i >> 4;
    int oc = t1 % OCP;
    int tcc = t1 / OCP;
    int cc = tcc & 3;
    int tp = tcc >> 2;
    int c = cc * 16 + cic;
    float v = 0.f;
    if (oc < OCH_OFF)      v = w_off[((size_t)oc * CIN + c) * 9 + tp];
    else if (oc < OCH_TOT) v = w_mod[((size_t)(oc - OCH_OFF) * CIN + c) * 9 + tp];
    __nv_bfloat16 h = __float2bfloat16(v);
    g_wa2_hi[i] = h;
    g_wa2_lo[i] = __float2bfloat16(v - __bfloat162float(h));
}

__global__ void transpose_wconv(const float* __restrict__ w_conv) {
    int i = blockIdx.x * 256 + threadIdx.x;
    if (i < OC_FIN * 576) {
        int oc = i / 576, ck = i % 576;
        g_wt[ck * 128 + oc] = w_conv[i];
    }
}

// ======================= Conv kernel: mma.sync bf16 =======================
// CTA: 128 oc x 128 px (2 image rows of one b). 8 warps: wm = w&3 (oc quad),
// wn = w>>2 (image row). Warp tile 32 oc x 64 px. K = 9 taps x 4 chunks of 16.
// SMEM: double buffer of {A[128][24]bf16 hi,lo ; B[128][24]bf16 hi,lo}
//   row stride 48 B (16 data + 8 pad bf16) -> conflict-free ldmatrix.
#define SROW 48
#define AHALF 6144             // 128*48
#define BUFSZ 24576            // A(hi+lo) + B(hi+lo)
__global__ __launch_bounds__(256) void conv_mma_kernel(
    const float* __restrict__ b_off, const float* __restrict__ b_mod)
{
    __shared__ __align__(16) char smem[2 * BUFSZ];   // 48 KB exactly
    const uint32_t sb = smem_u32(smem);
    const int tid = threadIdx.x;
    const int lane = tid & 31;
    const int w = tid >> 5;
    const int wm = w & 3;
    const int wn = w >> 2;
    const int ocBase = blockIdx.x * 128;
    const int y0 = blockIdx.y * 2;
    const int b  = blockIdx.z;

    float d[2][8][4];
#pragma unroll
    for (int mt = 0; mt < 2; mt++)
#pragma unroll
        for (int nt = 0; nt < 8; nt++)
#pragma unroll
            for (int e = 0; e < 4; e++) d[mt][nt][e] = 0.f;

    // staging lambda-ish: load k-step s into buffer buf
    // s: t = s>>2 (tap), cc = s&3
    auto stage = [&](int s, int buf) {
        const int t = s >> 2, cc = s & 3;
        const int ki = t / 3, kj = t - ki * 3;
        char* dstA = smem + buf * BUFSZ;
        char* dstB = smem + buf * BUFSZ + 2 * AHALF;
        // A: 2 halves x 128 oc x 2 j(16B)
        // B: 2 halves x 128 px x 2 j(16B)
#pragma unroll
        for (int ii = 0; ii < 4; ii++) {
            int i = tid + ii * 256;
            if (i < 512) {
                int hh = i >> 8, oc = (i >> 1) & 127, j = i & 1;
                const __nv_bfloat16* src = (hh ? g_wa2_lo : g_wa2_hi)
                    + (((size_t)(t * 4 + cc) * OCP + ocBase + oc) << 4) + j * 8;
                *(uint4*)(dstA + hh * AHALF + oc * SROW + j * 16) = *(const uint4*)src;
            } else {
                i -= 512;
                int hh = i >> 8, px = (i >> 1) & 127, j = i & 1;
                int yy = y0 + (px >> 6) + ki;
                const __nv_bfloat16* src = (hh ? g_xt2_lo : g_xt2_hi)
                    + (((size_t)(((kj * 8 + b) * 66 + yy) * 4 + cc) * 64 + (px & 63)) << 4)
                    + j * 8;
                *(uint4*)(dstB + hh * AHALF + px * SROW + j * 16) = *(const uint4*)src;
            }
        }
    };

    stage(0, 0);
    __syncthreads();

    const int arowL = (lane & 7) + ((lane >> 3) & 1) * 8;  // row within 16
    const int acolB = ((lane >> 4) & 1) * 16;              // 0 or 16 bytes

    for (int s = 0; s < 36; s++) {
        const int buf = s & 1;
        if (s + 1 < 36) stage(s + 1, 1 - buf);

        const uint32_t sA = sb + buf * BUFSZ;
        const uint32_t sB = sA + 2 * AHALF;

        // A fragments: [mt][half][4]
        uint32_t a[2][2][4];
#pragma unroll
        for (int mt = 0; mt < 2; mt++)
#pragma unroll
            for (int hh = 0; hh < 2; hh++)
                ldm_x4(a[mt][hh],
                       sA + hh * AHALF + (wm * 32 + mt * 16 + arowL) * SROW + acolB);

#pragma unroll
        for (int p = 0; p < 4; p++) {
            uint32_t bh[4], bl[4];
            uint32_t baddr = sB + (wn * 64 + p * 16 + arowL) * SROW + acolB;
            ldm_x4(bh, baddr);
            ldm_x4(bl, baddr + AHALF);
#pragma unroll
            for (int mt = 0; mt < 2; mt++) {
#pragma unroll
                for (int q = 0; q < 2; q++) {
                    float* dd = d[mt][p * 2 + q];
                    mma_bf16(dd, a[mt][0], bh[q], bh[q + 2]);   // Ah*Bh
                    mma_bf16(dd, a[mt][0], bl[q], bl[q + 2]);   // Ah*Bl
                    mma_bf16(dd, a[mt][1], bh[q], bh[q + 2]);   // Al*Bh
                }
            }
        }
        __syncthreads();
    }

    // epilogue: bias + clip + store. Warp-uniform oc validity (1728 = 1664+64).
    const int ocW = ocBase + wm * 32;
    if (ocW >= OCH_TOT) return;
    const int y = y0 + wn;
#pragma unroll
    for (int mt = 0; mt < 2; mt++) {
        int r0 = ocW + mt * 16 + (lane >> 2);
        int r1 = r0 + 8;
        float bias0 = (r0 < OCH_OFF) ? __ldg(&b_off[r0]) : __ldg(&b_mod[r0 - OCH_OFF]);
        float bias1 = (r1 < OCH_OFF) ? __ldg(&b_off[r1]) : __ldg(&b_mod[r1 - OCH_OFF]);
        bool c0 = r0 < OCH_OFF, c1 = r1 < OCH_OFF;
        float* base0 = &g_om[(((size_t)b * OCH_TOT + r0) * HH + y) * WW];
        float* base1 = &g_om[(((size_t)b * OCH_TOT + r1) * HH + y) * WW];
#pragma unroll
        for (int nt = 0; nt < 8; nt++) {
            int col = nt * 8 + (lane & 3) * 2;
            float2 v0, v1;
            v0.x = d[mt][nt][0] + bias0; v0.y = d[mt][nt][1] + bias0;
            v1.x = d[mt][nt][2] + bias1; v1.y = d[mt][nt][3] + bias1;
            if (c0) {
                v0.x = fminf(fmaxf(v0.x, -MAXOFF), MAXOFF);
                v0.y = fminf(fmaxf(v0.y, -MAXOFF), MAXOFF);
            }
            if (c1) {
                v1.x = fminf(fmaxf(v1.x, -MAXOFF), MAXOFF);
                v1.y = fminf(fmaxf(v1.y, -MAXOFF), MAXOFF);
            }
            *(float2*)(base0 + col) = v0;
            *(float2*)(base1 + col) = v1;
        }
    }
}

// ======================= Deform + final GEMM =======================
__global__ __launch_bounds__(256) void deform_gemm_kernel(
    const float* __restrict__ x,
    float* __restrict__ out)
{
    const int y = blockIdx.x;
    const int b = blockIdx.y;
    const int tid = threadIdx.x;
    const int tx = tid & 15;
    const int ty = tid >> 4;
    const int px0 = tx * 4;
    const int oc0 = ty * 8;

    __shared__ __align__(16) float ss[4 * 9 * 64];
    __shared__ __align__(16) float wcs[36][128];

    unsigned long long acc2[4][4];
#pragma unroll
    for (int p = 0; p < 4; p++)
#pragma unroll
        for (int j = 0; j < 4; j++) acc2[p][j] = 0ull;

    const float* xb  = x + (size_t)b * CIN * HH * WW;
    const float* omb = g_om + (size_t)b * OCH_TOT * HH * WW;

    for (int c0 = 0; c0 < CIN; c0 += 4) {
        for (int idx = tid; idx < 36 * 128; idx += 256) {
            ((float*)wcs)[idx] = g_wt[(c0 * 9 + (idx >> 7)) * 128 + (idx & 127)];
        }
        for (int s = tid; s < 4 * 9 * 64; s += 256) {
            int px = s & 63;
            int k  = (s >> 6) % 9;
            int cc = s / 576;
            int c  = c0 + cc;
            int ki = k / 3, kj = k % 3;
            float dy = omb[(((size_t)c * 18 + k * 2 + 0) * HH + y) * WW + px];
            float dx = omb[(((size_t)c * 18 + k * 2 + 1) * HH + y) * WW + px];
            float m  = omb[(((size_t)OCH_OFF + c * 9 + k) * HH + y) * WW + px];
            float py  = dy + (float)(y - 1 + ki);
            float pxf = dx + (float)(px - 1 + kj);
            float v = 0.f;
            if (py > -1.f && py < (float)HH && pxf > -1.f && pxf < (float)WW) {
                float y0f = floorf(py), x0f = floorf(pxf);
                int y0 = (int)y0f, x0 = (int)x0f;
                float wy = py - y0f, wx = pxf - x0f;
                const float* xc = xb + (size_t)c * HH * WW;
                float v00 = 0.f, v01 = 0.f, v10 = 0.f, v11 = 0.f;
                bool y0i = (y0 >= 0) & (y0 < HH);
                bool y1i = (y0 + 1 >= 0) & (y0 + 1 < HH);
                bool x0i = (x0 >= 0) & (x0 < WW);
                bool x1i = (x0 + 1 >= 0) & (x0 + 1 < WW);
                if (y0i & x0i) v00 = __ldg(&xc[y0 * WW + x0]);
                if (y0i & x1i) v01 = __ldg(&xc[y0 * WW + x0 + 1]);
                if (y1i & x0i) v10 = __ldg(&xc[(y0 + 1) * WW + x0]);
                if (y1i & x1i) v11 = __ldg(&xc[(y0 + 1) * WW + x0 + 1]);
                v = (1.f - wy) * ((1.f - wx) * v00 + wx * v01)
                  +        wy  * ((1.f - wx) * v10 + wx * v11);
            }
            ss[s] = v * m;
        }
        __syncthreads();

#pragma unroll
        for (int ck = 0; ck < 36; ck++) {
            float4 sv4 = *(const float4*)&ss[ck * 64 + px0];
            unsigned long long sp[4];
            sp[0] = pack2(sv4.x, sv4.x);
            sp[1] = pack2(sv4.y, sv4.y);
            sp[2] = pack2(sv4.z, sv4.z);
            sp[3] = pack2(sv4.w, sv4.w);
            ulonglong2 w0 = *(const ulonglong2*)&wcs[ck][oc0];
            ulonglong2 w1 = *(const ulonglong2*)&wcs[ck][oc0 + 4];
#pragma unroll
            for (int j = 0; j < 4; j++) {
                acc2[0][j] = ffma2(w0.x, sp[j], acc2[0][j]);
                acc2[1][j] = ffma2(w0.y, sp[j], acc2[1][j]);
                acc2[2][j] = ffma2(w1.x, sp[j], acc2[2][j]);
                acc2[3][j] = ffma2(w1.y, sp[j], acc2[3][j]);
            }
        }
        __syncthreads();
    }

#pragma unroll
    for (int p = 0; p < 4; p++) {
        float lo[4], hi[4];
#pragma unroll
        for (int j = 0; j < 4; j++) unpack2(acc2[p][j], lo[j], hi[j]);
        float4 vlo = make_float4(lo[0], lo[1], lo[2], lo[3]);
        float4 vhi = make_float4(hi[0], hi[1], hi[2], hi[3]);
        int oc = oc0 + 2 * p;
        *(float4*)&out[(((size_t)b * OC_FIN + oc) * HH + y) * WW + px0] = vlo;
        *(float4*)&out[(((size_t)b * OC_FIN + oc + 1) * HH + y) * WW + px0] = vhi;
    }
}

// ---------------------------------------------------------------------------
extern "C" void kernel_launch(void* const* d_in, const int* in_sizes, int n_in,
                              void* d_out, int out_size)
{
    const float* x      = (const float*)d_in[0];
    const float* w_off  = (const float*)d_in[1];
    const float* b_off  = (const float*)d_in[2];
    const float* w_mod  = (const float*)d_in[3];
    const float* b_mod  = (const float*)d_in[4];
    const float* w_conv = (const float*)d_in[5];
    float* out = (float*)d_out;

    prep_xt2<<<(3 * 8 * 66 * 4 * 64 * 16 + 255) / 256, 256>>>(x);
    prep_w2<<<(9 * 4 * OCP * 16 + 255) / 256, 256>>>(w_off, w_mod);
    conv_mma_kernel<<<dim3(14, 32, 8), 256>>>(b_off, b_mod);
    transpose_wconv<<<(OC_FIN * 576 + 255) / 256, 256>>>(w_conv);
    deform_gemm_kernel<<<dim3(HH, BB), 256>>>(x, out);
}